// round 16
// baseline (speedup 1.0000x reference)
#include <cuda_runtime.h>
#include <cuda_bf16.h>
#include <cstdint>

// ---------------------------------------------------------------------------
// Voxelizer: volume[z,y,x] = sum_n density[n] * exp(-0.5 * d^T C_n^{-1} d)
//
// R15 (resubmit; prior run was an infra failure): R14 math + the R12 split
//      done right (no atomics):
//      - each tile processed by TWO blocks (gaussian half 0 / half 1);
//        half 0 writes d_out, half 1 writes a __device__ scratch buffer,
//        both with plain float4 stores. A combine kernel adds them.
//      - 2048 blocks > 1184 residency -> 1.73 waves, HW backfill balances
//        (R14 issue=48% was static-schedule drain). Deterministic.
//      - cut 24, warp-uniform parabola-max skip, anisotropic+sphere cull,
//        packed f32x2 two-row pipeline, stride-2 recurrence, (128,8).
// ---------------------------------------------------------------------------

#define MAX_N 4096
__device__ float4 g_gauss[3 * MAX_N];
__device__ float4 g_cull[5 * MAX_N];
__device__ float g_partial[128 * 128 * 128];   // half-1 accumulator (8 MB)

#define DIMX 128
#define DIMY 128
#define DIMZ 128
#define RUNX 8
#define TILE_Y 16
#define TILE_Z 16
#define HSTEP (2.0f / 127.0f)
#define CUT 24.0f

typedef unsigned long long u64;

__device__ __forceinline__ float ex2_approx(float x) {
    float y;
    asm("ex2.approx.ftz.f32 %0, %1;" : "=f"(y) : "f"(x));
    return y;
}
__device__ __forceinline__ u64 pk2(float lo, float hi) {
    u64 p;
    asm("mov.b64 %0, {%1, %2};" : "=l"(p) : "r"(__float_as_uint(lo)), "r"(__float_as_uint(hi)));
    return p;
}
__device__ __forceinline__ u64 pkb(float x) { return pk2(x, x); }
__device__ __forceinline__ void upk2(u64 p, float& lo, float& hi) {
    unsigned a, b;
    asm("mov.b64 {%0, %1}, %2;" : "=r"(a), "=r"(b) : "l"(p));
    lo = __uint_as_float(a); hi = __uint_as_float(b);
}
__device__ __forceinline__ u64 pfma(u64 a, u64 b, u64 c) {
    u64 d;
    asm("fma.rn.f32x2 %0, %1, %2, %3;" : "=l"(d) : "l"(a), "l"(b), "l"(c));
    return d;
}
__device__ __forceinline__ u64 pmul(u64 a, u64 b) {
    u64 d;
    asm("mul.rn.f32x2 %0, %1, %2;" : "=l"(d) : "l"(a), "l"(b));
    return d;
}

__global__ void precompute_kernel(const float* __restrict__ pos,
                                  const float* __restrict__ scl,
                                  const float* __restrict__ rot,
                                  const float* __restrict__ den,
                                  int N) {
    int i = blockIdx.x * blockDim.x + threadIdx.x;
    if (i >= N) return;

    float qw = rot[4 * i + 0], qx = rot[4 * i + 1];
    float qy = rot[4 * i + 2], qz = rot[4 * i + 3];
    float qn = rsqrtf(qw * qw + qx * qx + qy * qy + qz * qz);
    qw *= qn; qx *= qn; qy *= qn; qz *= qn;

    float r00 = 1.f - 2.f * (qy * qy + qz * qz);
    float r01 = 2.f * (qx * qy - qw * qz);
    float r02 = 2.f * (qx * qz + qw * qy);
    float r10 = 2.f * (qx * qy + qw * qz);
    float r11 = 1.f - 2.f * (qx * qx + qz * qz);
    float r12 = 2.f * (qy * qz - qw * qx);
    float r20 = 2.f * (qx * qz - qw * qy);
    float r21 = 2.f * (qy * qz + qw * qx);
    float r22 = 1.f - 2.f * (qx * qx + qy * qy);

    float s0 = scl[3 * i + 0], s1 = scl[3 * i + 1], s2 = scl[3 * i + 2];
    float i0 = 1.f / (s0 * s0 + 1e-8f);
    float i1 = 1.f / (s1 * s1 + 1e-8f);
    float i2 = 1.f / (s2 * s2 + 1e-8f);

    float c00 = r00 * r00 * i0 + r01 * r01 * i1 + r02 * r02 * i2;
    float c11 = r10 * r10 * i0 + r11 * r11 * i1 + r12 * r12 * i2;
    float c22 = r20 * r20 * i0 + r21 * r21 * i1 + r22 * r22 * i2;
    float c01 = r00 * r10 * i0 + r01 * r11 * i1 + r02 * r12 * i2;
    float c02 = r00 * r20 * i0 + r01 * r21 * i1 + r02 * r22 * i2;
    float c12 = r10 * r20 * i0 + r11 * r21 * i1 + r12 * r22 * i2;

    const float k = -0.5f * 1.4426950408889634f;  // exp(-0.5m) = 2^(k*m)

    float smax2 = fmaxf(s0 * s0, fmaxf(s1 * s1, s2 * s2)) + 1e-8f;
    float rcut2 = CUT * smax2;  // skipped term <= exp(-12) ~ 6.1e-6

    float p0 = pos[3 * i + 0];  // z
    float p1 = pos[3 * i + 1];  // y
    float p2 = pos[3 * i + 2];  // x (fast axis)

    float a  = k * c22;                         // coef of dx^2 (log2, < 0)
    float rr = exp2f(2.f * a * HSTEP * HSTEP);  // per-step G ratio, (0.5,1]
    float inv4a = -0.25f / a;                   // 0.25/|a| > 0

    // ---- main-loop params (3 x float4) ----
    g_gauss[3 * i + 0] = make_float4(a, k * c11, k * c00, 2.f * k * c12);
    g_gauss[3 * i + 1] = make_float4(2.f * k * c02, 2.f * k * c01, p2, p1);
    g_gauss[3 * i + 2] = make_float4(p0, den[i], inv4a, rr);

    // ---- cull params (5 x float4) ----
    const float hz = (TILE_Z - 1) * 0.5f * HSTEP;
    const float hy = (TILE_Y - 1) * 0.5f * HSTEP;
    const float hx = (RUNX   - 1) * 0.5f * HSTEP;
    float rho0 = fabsf(r00) * hz + fabsf(r10) * hy + fabsf(r20) * hx;
    float rho1 = fabsf(r01) * hz + fabsf(r11) * hy + fabsf(r21) * hx;
    float rho2 = fabsf(r02) * hz + fabsf(r12) * hy + fabsf(r22) * hx;
    g_cull[5 * i + 0] = make_float4(r00, r10, r20, rho0);
    g_cull[5 * i + 1] = make_float4(r01, r11, r21, rho1);
    g_cull[5 * i + 2] = make_float4(r02, r12, r22, rho2);
    g_cull[5 * i + 3] = make_float4(i0, i1, i2, rcut2);
    g_cull[5 * i + 4] = make_float4(p0, p1, p2, 0.f);      // (z, y, x)
}

// out[i] = out[i] + partial[i]  (deterministic two-operand add)
__global__ void combine_kernel(float4* __restrict__ out, int n4) {
    int i = blockIdx.x * blockDim.x + threadIdx.x;
    if (i < n4) {
        const float4 p = reinterpret_cast<const float4*>(g_partial)[i];
        float4 o = out[i];
        o.x += p.x; o.y += p.y; o.z += p.z; o.w += p.w;
        out[i] = o;
    }
}

// Tile: 8(x) x 16(y) x 16(z); 128 threads, each owns rows (ty, ty+8) x 8 x.
// grid.z packs (z-tile, gaussian-half): bz = z & 7, half = z >> 3.
// half 0 -> d_out, half 1 -> g_partial; both plain stores (no atomics).
__global__ __launch_bounds__(128, 8)
void voxelize_kernel(float* __restrict__ out, int N) {
    __shared__ float4 sg[3 * 256];
    __shared__ int slist[256];
    __shared__ int swcnt[4];

    const float h = HSTEP;
    const int tid  = threadIdx.x;
    const int lane = tid & 31;
    const int wid  = tid >> 5;

    const int ty = tid & 7;         // y in [0,8); second row at ty+8
    const int tz = tid >> 3;        // z in [0,16)

    const int bz   = blockIdx.z & 7;
    const int half = blockIdx.z >> 3;
    const int Nh     = (N + 1) >> 1;
    const int nstart = half ? Nh : 0;
    const int nend   = half ? N : Nh;
    float* dst = half ? g_partial : out;

    const int gx = blockIdx.x * RUNX;
    const int gy = blockIdx.y * TILE_Y + ty;
    const int gz = bz * TILE_Z + tz;

    const float x0  = -1.f + h * (float)gx;
    const float vyA = -1.f + h * (float)gy;
    const float vz  = -1.f + h * (float)gz;

    const float cx = -1.f + h * ((float)(blockIdx.x * RUNX)   + (RUNX   - 1) * 0.5f);
    const float cy = -1.f + h * ((float)(blockIdx.y * TILE_Y) + (TILE_Y - 1) * 0.5f);
    const float cz = -1.f + h * ((float)(bz * TILE_Z)         + (TILE_Z - 1) * 0.5f);
    const float hx = (RUNX   - 1) * 0.5f * h;
    const float hy = (TILE_Y - 1) * 0.5f * h;
    const float hz = (TILE_Z - 1) * 0.5f * h;

    u64 acc2[RUNX];  // lane0 = row A (gy), lane1 = row B (gy+8)
#pragma unroll
    for (int v = 0; v < RUNX; v++) acc2[v] = 0ull;

    for (int base = nstart; base < nend; base += 256) {
        const int nch = min(256, nend - base);

        for (int j = tid; j < 3 * nch; j += 128)
            sg[j] = g_gauss[3 * (base) + j];
        __syncthreads();

        // Cull: anisotropic interval bound AND sphere bound.
        int cnt = 0;
#pragma unroll
        for (int hh = 0; hh < 2; hh++) {
            const int c = hh * 128 + tid;
            bool keep = false;
            if (c < nch) {
                const float4 u0c = g_cull[5 * (base + c) + 0];
                const float4 u1c = g_cull[5 * (base + c) + 1];
                const float4 u2c = g_cull[5 * (base + c) + 2];
                const float4 u3c = g_cull[5 * (base + c) + 3];
                const float4 u4c = g_cull[5 * (base + c) + 4];

                const float d0 = cz - u4c.x;
                const float d1 = cy - u4c.y;
                const float d2 = cx - u4c.z;

                const float q0 = u0c.x * d0 + u0c.y * d1 + u0c.z * d2;
                const float q1 = u1c.x * d0 + u1c.y * d1 + u1c.z * d2;
                const float q2 = u2c.x * d0 + u2c.y * d1 + u2c.z * d2;

                const float t0 = fmaxf(fabsf(q0) - u0c.w, 0.f);
                const float t1 = fmaxf(fabsf(q1) - u1c.w, 0.f);
                const float t2 = fmaxf(fabsf(q2) - u2c.w, 0.f);
                const float mlow = t0 * t0 * u3c.x + t1 * t1 * u3c.y + t2 * t2 * u3c.z;

                const float ex = fmaxf(fabsf(d2) - hx, 0.f);
                const float ey = fmaxf(fabsf(d1) - hy, 0.f);
                const float ez = fmaxf(fabsf(d0) - hz, 0.f);
                const float dsph = ex * ex + ey * ey + ez * ez;

                keep = (mlow <= CUT) && (dsph <= u3c.w);
            }
            unsigned m = __ballot_sync(0xffffffffu, keep);
            if (lane == 0) swcnt[wid] = __popc(m);
            __syncthreads();
            int wbase = cnt;
#pragma unroll
            for (int w = 0; w < 4; w++)
                if (w < wid) wbase += swcnt[w];
            if (keep)
                slist[wbase + __popc(m & ((1u << lane) - 1u))] = c;
            cnt += swcnt[0] + swcnt[1] + swcnt[2] + swcnt[3];
            __syncthreads();
        }

        for (int g = 0; g < cnt; g++) {
            const int idx = slist[g];
            const float4 f0 = sg[3 * idx + 0];
            const float4 f1 = sg[3 * idx + 1];
            const float4 f2 = sg[3 * idx + 2];

            // Scalar (row-independent) setup
            const float dz  = vz - f2.x;
            const float u0  = x0 - f1.z;
            const float bxz = f1.x * dz;          // 2k*c02*dz
            const float t1  = f1.y * dz;          // 2k*c01*dz
            const float t2  = (f0.z * dz) * dz;   // k*c00*dz^2
            const float dyA = vyA - f1.w;
            const float dyB = dyA + 8.f * h;

            // Packed: lane0=row A, lane1=row B
            const u64 dy2 = pk2(dyA, dyB);
            const u64 bb2 = pfma(pkb(f0.w), dy2, pkb(bxz));
            const u64 cc2 = pfma(dy2, pfma(pkb(f0.y), dy2, pkb(t1)), pkb(t2));

            // Parabola max (log2): m_ub = cc + bb^2 * (0.25/|a|).
            const u64 ub2 = pfma(pmul(bb2, bb2), pkb(f2.z), cc2);
            float ubA, ubB;
            upk2(ub2, ubA, ubB);
            const bool dead = fmaxf(ubA, ubB) < -28.f;
            if (__all_sync(0xffffffffu, dead)) continue;

            const float r   = f2.w;
            const float r2s = r * r;
            const float r4s = r2s * r2s;

            const u64 a2  = pkb(f0.x);
            const u64 u02 = pkb(u0);
            const u64 m02 = pfma(pfma(a2, u02, bb2), u02, cc2);
            // step exponent g = h*(a*(2u0+h) + bb)
            const u64 g2  = pmul(pfma(a2, pkb(2.f * u0 + h), bb2), pkb(h));

            float m0A, m0B, gA, gB;
            upk2(m02, m0A, m0B);
            upk2(g2, gA, gB);
            gA = fminf(gA, 16.f);
            gB = fminf(gB, 16.f);

            u64 E0 = pk2(ex2_approx(m0A), ex2_approx(m0B));
            u64 G0 = pk2(ex2_approx(gA), ex2_approx(gB));
            const u64 rp  = pkb(r);
            const u64 rp2 = pkb(r2s);
            const u64 rp4 = pkb(r4s);
            const u64 w2  = pkb(f2.y);

            // Even/odd stride-2 chains: E_{v+2}=E_v*H_v ; H_{v+2}=H_v*r^4
            const u64 E1 = pmul(E0, G0);
            const u64 H0 = pmul(pmul(G0, G0), rp);
            const u64 H1 = pmul(H0, rp2);
            const u64 E2 = pmul(E0, H0);
            const u64 E3 = pmul(E1, H1);
            const u64 H2 = pmul(H0, rp4);
            const u64 H3 = pmul(H1, rp4);
            const u64 E4 = pmul(E2, H2);
            const u64 E5 = pmul(E3, H3);
            const u64 H4 = pmul(H2, rp4);
            const u64 H5 = pmul(H3, rp4);
            const u64 E6 = pmul(E4, H4);
            const u64 E7 = pmul(E5, H5);

            acc2[0] = pfma(E0, w2, acc2[0]);
            acc2[1] = pfma(E1, w2, acc2[1]);
            acc2[2] = pfma(E2, w2, acc2[2]);
            acc2[3] = pfma(E3, w2, acc2[3]);
            acc2[4] = pfma(E4, w2, acc2[4]);
            acc2[5] = pfma(E5, w2, acc2[5]);
            acc2[6] = pfma(E6, w2, acc2[6]);
            acc2[7] = pfma(E7, w2, acc2[7]);
        }
        __syncthreads();
    }

    float accA[RUNX], accB[RUNX];
#pragma unroll
    for (int v = 0; v < RUNX; v++) upk2(acc2[v], accA[v], accB[v]);

    const size_t vA = ((size_t)gz * DIMY + gy) * DIMX + gx;
    const size_t vB = ((size_t)gz * DIMY + (gy + 8)) * DIMX + gx;
    *reinterpret_cast<float4*>(dst + vA)     = make_float4(accA[0], accA[1], accA[2], accA[3]);
    *reinterpret_cast<float4*>(dst + vA + 4) = make_float4(accA[4], accA[5], accA[6], accA[7]);
    *reinterpret_cast<float4*>(dst + vB)     = make_float4(accB[0], accB[1], accB[2], accB[3]);
    *reinterpret_cast<float4*>(dst + vB + 4) = make_float4(accB[4], accB[5], accB[6], accB[7]);
}

extern "C" void kernel_launch(void* const* d_in, const int* in_sizes, int n_in,
                              void* d_out, int out_size) {
    const float* positions = (const float*)d_in[0];
    const float* scales    = (const float*)d_in[1];
    const float* rotations = (const float*)d_in[2];
    const float* density   = (const float*)d_in[3];
    const int N = in_sizes[3];

    precompute_kernel<<<(N + 255) / 256, 256>>>(positions, scales, rotations, density, N);

    // grid.z = 16: low 3 bits = z-tile, bit 3 = gaussian half
    dim3 grid(DIMX / RUNX, DIMY / TILE_Y, 2 * (DIMZ / TILE_Z));  // 2048 blocks
    voxelize_kernel<<<grid, 128>>>((float*)d_out, N);

    const int n4 = out_size / 4;
    combine_kernel<<<(n4 + 255) / 256, 256>>>((float4*)d_out, n4);
}

// round 17
// speedup vs baseline: 1.1897x; 1.1897x over previous
#include <cuda_runtime.h>
#include <cuda_bf16.h>
#include <cstdint>

// ---------------------------------------------------------------------------
// Voxelizer: volume[z,y,x] = sum_n density[n] * exp(-0.5 * d^T C_n^{-1} d)
//
// R17: R14 math, half-size tiles for schedulable granularity:
//      - tile 8x x 16y x 8z, 64-thread blocks (2 warps), 2048 blocks.
//        Per-warp footprint and inner loop IDENTICAL to R14; only the
//        block granularity halves. Plain disjoint stores (no atomics,
//        no combine, no zero pass).
//      - __launch_bounds__(64,12): 24 warps/SM, capacity 1776 < 2048 ->
//        1.15 waves (dynamic tail) + 2x static tiles/SM (sqrt(2) less
//        statistical imbalance).
//      - cut 24, parabola-max warp skip, anisotropic+sphere cull,
//        packed f32x2 two-row pipeline, stride-2 recurrence.
// ---------------------------------------------------------------------------

#define MAX_N 4096
__device__ float4 g_gauss[3 * MAX_N];
__device__ float4 g_cull[5 * MAX_N];

#define DIMX 128
#define DIMY 128
#define DIMZ 128
#define RUNX 8
#define TILE_Y 16
#define TILE_Z 8
#define NTHREADS 64
#define HSTEP (2.0f / 127.0f)
#define CUT 24.0f

typedef unsigned long long u64;

__device__ __forceinline__ float ex2_approx(float x) {
    float y;
    asm("ex2.approx.ftz.f32 %0, %1;" : "=f"(y) : "f"(x));
    return y;
}
__device__ __forceinline__ u64 pk2(float lo, float hi) {
    u64 p;
    asm("mov.b64 %0, {%1, %2};" : "=l"(p) : "r"(__float_as_uint(lo)), "r"(__float_as_uint(hi)));
    return p;
}
__device__ __forceinline__ u64 pkb(float x) { return pk2(x, x); }
__device__ __forceinline__ void upk2(u64 p, float& lo, float& hi) {
    unsigned a, b;
    asm("mov.b64 {%0, %1}, %2;" : "=r"(a), "=r"(b) : "l"(p));
    lo = __uint_as_float(a); hi = __uint_as_float(b);
}
__device__ __forceinline__ u64 pfma(u64 a, u64 b, u64 c) {
    u64 d;
    asm("fma.rn.f32x2 %0, %1, %2, %3;" : "=l"(d) : "l"(a), "l"(b), "l"(c));
    return d;
}
__device__ __forceinline__ u64 pmul(u64 a, u64 b) {
    u64 d;
    asm("mul.rn.f32x2 %0, %1, %2;" : "=l"(d) : "l"(a), "l"(b));
    return d;
}

__global__ void precompute_kernel(const float* __restrict__ pos,
                                  const float* __restrict__ scl,
                                  const float* __restrict__ rot,
                                  const float* __restrict__ den,
                                  int N) {
    int i = blockIdx.x * blockDim.x + threadIdx.x;
    if (i >= N) return;

    float qw = rot[4 * i + 0], qx = rot[4 * i + 1];
    float qy = rot[4 * i + 2], qz = rot[4 * i + 3];
    float qn = rsqrtf(qw * qw + qx * qx + qy * qy + qz * qz);
    qw *= qn; qx *= qn; qy *= qn; qz *= qn;

    float r00 = 1.f - 2.f * (qy * qy + qz * qz);
    float r01 = 2.f * (qx * qy - qw * qz);
    float r02 = 2.f * (qx * qz + qw * qy);
    float r10 = 2.f * (qx * qy + qw * qz);
    float r11 = 1.f - 2.f * (qx * qx + qz * qz);
    float r12 = 2.f * (qy * qz - qw * qx);
    float r20 = 2.f * (qx * qz - qw * qy);
    float r21 = 2.f * (qy * qz + qw * qx);
    float r22 = 1.f - 2.f * (qx * qx + qy * qy);

    float s0 = scl[3 * i + 0], s1 = scl[3 * i + 1], s2 = scl[3 * i + 2];
    float i0 = 1.f / (s0 * s0 + 1e-8f);
    float i1 = 1.f / (s1 * s1 + 1e-8f);
    float i2 = 1.f / (s2 * s2 + 1e-8f);

    float c00 = r00 * r00 * i0 + r01 * r01 * i1 + r02 * r02 * i2;
    float c11 = r10 * r10 * i0 + r11 * r11 * i1 + r12 * r12 * i2;
    float c22 = r20 * r20 * i0 + r21 * r21 * i1 + r22 * r22 * i2;
    float c01 = r00 * r10 * i0 + r01 * r11 * i1 + r02 * r12 * i2;
    float c02 = r00 * r20 * i0 + r01 * r21 * i1 + r02 * r22 * i2;
    float c12 = r10 * r20 * i0 + r11 * r21 * i1 + r12 * r22 * i2;

    const float k = -0.5f * 1.4426950408889634f;  // exp(-0.5m) = 2^(k*m)

    float smax2 = fmaxf(s0 * s0, fmaxf(s1 * s1, s2 * s2)) + 1e-8f;
    float rcut2 = CUT * smax2;  // skipped term <= exp(-12) ~ 6.1e-6

    float p0 = pos[3 * i + 0];  // z
    float p1 = pos[3 * i + 1];  // y
    float p2 = pos[3 * i + 2];  // x (fast axis)

    float a  = k * c22;                         // coef of dx^2 (log2, < 0)
    float rr = exp2f(2.f * a * HSTEP * HSTEP);  // per-step G ratio, (0.5,1]
    float inv4a = -0.25f / a;                   // 0.25/|a| > 0

    // ---- main-loop params (3 x float4) ----
    g_gauss[3 * i + 0] = make_float4(a, k * c11, k * c00, 2.f * k * c12);
    g_gauss[3 * i + 1] = make_float4(2.f * k * c02, 2.f * k * c01, p2, p1);
    g_gauss[3 * i + 2] = make_float4(p0, den[i], inv4a, rr);

    // ---- cull params (5 x float4) ---- (tile half-extents: 8x16y8z tile)
    const float hz = (TILE_Z - 1) * 0.5f * HSTEP;
    const float hy = (TILE_Y - 1) * 0.5f * HSTEP;
    const float hx = (RUNX   - 1) * 0.5f * HSTEP;
    float rho0 = fabsf(r00) * hz + fabsf(r10) * hy + fabsf(r20) * hx;
    float rho1 = fabsf(r01) * hz + fabsf(r11) * hy + fabsf(r21) * hx;
    float rho2 = fabsf(r02) * hz + fabsf(r12) * hy + fabsf(r22) * hx;
    g_cull[5 * i + 0] = make_float4(r00, r10, r20, rho0);
    g_cull[5 * i + 1] = make_float4(r01, r11, r21, rho1);
    g_cull[5 * i + 2] = make_float4(r02, r12, r22, rho2);
    g_cull[5 * i + 3] = make_float4(i0, i1, i2, rcut2);
    g_cull[5 * i + 4] = make_float4(p0, p1, p2, 0.f);      // (z, y, x)
}

// Tile: 8(x) x 16(y) x 8(z); 64 threads (2 warps), each owns rows
// (ty, ty+8) x 8 x. Same per-warp footprint/inner loop as R14.
__global__ __launch_bounds__(NTHREADS, 12)
void voxelize_kernel(float* __restrict__ out, int N) {
    __shared__ float4 sg[3 * 256];
    __shared__ int slist[256];
    __shared__ int swcnt[2];

    const float h = HSTEP;
    const int tid  = threadIdx.x;
    const int lane = tid & 31;
    const int wid  = tid >> 5;          // 0 or 1

    const int ty = tid & 7;             // y in [0,8); second row at ty+8
    const int tz = tid >> 3;            // z in [0,8)

    const int gx = blockIdx.x * RUNX;
    const int gy = blockIdx.y * TILE_Y + ty;
    const int gz = blockIdx.z * TILE_Z + tz;

    const float x0  = -1.f + h * (float)gx;
    const float vyA = -1.f + h * (float)gy;
    const float vz  = -1.f + h * (float)gz;

    const float cx = -1.f + h * ((float)(blockIdx.x * RUNX)   + (RUNX   - 1) * 0.5f);
    const float cy = -1.f + h * ((float)(blockIdx.y * TILE_Y) + (TILE_Y - 1) * 0.5f);
    const float cz = -1.f + h * ((float)(blockIdx.z * TILE_Z) + (TILE_Z - 1) * 0.5f);
    const float hx = (RUNX   - 1) * 0.5f * h;
    const float hy = (TILE_Y - 1) * 0.5f * h;
    const float hz = (TILE_Z - 1) * 0.5f * h;

    u64 acc2[RUNX];  // lane0 = row A (gy), lane1 = row B (gy+8)
#pragma unroll
    for (int v = 0; v < RUNX; v++) acc2[v] = 0ull;

    for (int base = 0; base < N; base += 256) {
        const int nch = min(256, N - base);

        for (int j = tid; j < 3 * nch; j += NTHREADS)
            sg[j] = g_gauss[3 * base + j];
        __syncthreads();

        // Cull: anisotropic interval bound AND sphere bound.
        // 256 candidates / 64 threads = 4 deterministic compaction passes.
        int cnt = 0;
#pragma unroll
        for (int hh = 0; hh < 4; hh++) {
            const int c = hh * NTHREADS + tid;
            bool keep = false;
            if (c < nch) {
                const float4 u0c = g_cull[5 * (base + c) + 0];
                const float4 u1c = g_cull[5 * (base + c) + 1];
                const float4 u2c = g_cull[5 * (base + c) + 2];
                const float4 u3c = g_cull[5 * (base + c) + 3];
                const float4 u4c = g_cull[5 * (base + c) + 4];

                const float d0 = cz - u4c.x;
                const float d1 = cy - u4c.y;
                const float d2 = cx - u4c.z;

                const float q0 = u0c.x * d0 + u0c.y * d1 + u0c.z * d2;
                const float q1 = u1c.x * d0 + u1c.y * d1 + u1c.z * d2;
                const float q2 = u2c.x * d0 + u2c.y * d1 + u2c.z * d2;

                const float t0 = fmaxf(fabsf(q0) - u0c.w, 0.f);
                const float t1 = fmaxf(fabsf(q1) - u1c.w, 0.f);
                const float t2 = fmaxf(fabsf(q2) - u2c.w, 0.f);
                const float mlow = t0 * t0 * u3c.x + t1 * t1 * u3c.y + t2 * t2 * u3c.z;

                const float ex = fmaxf(fabsf(d2) - hx, 0.f);
                const float ey = fmaxf(fabsf(d1) - hy, 0.f);
                const float ez = fmaxf(fabsf(d0) - hz, 0.f);
                const float dsph = ex * ex + ey * ey + ez * ez;

                keep = (mlow <= CUT) && (dsph <= u3c.w);
            }
            unsigned m = __ballot_sync(0xffffffffu, keep);
            if (lane == 0) swcnt[wid] = __popc(m);
            __syncthreads();
            int wbase = cnt + (wid ? swcnt[0] : 0);
            if (keep)
                slist[wbase + __popc(m & ((1u << lane) - 1u))] = c;
            cnt += swcnt[0] + swcnt[1];
            __syncthreads();
        }

        for (int g = 0; g < cnt; g++) {
            const int idx = slist[g];
            const float4 f0 = sg[3 * idx + 0];
            const float4 f1 = sg[3 * idx + 1];
            const float4 f2 = sg[3 * idx + 2];

            // Scalar (row-independent) setup
            const float dz  = vz - f2.x;
            const float u0  = x0 - f1.z;
            const float bxz = f1.x * dz;          // 2k*c02*dz
            const float t1  = f1.y * dz;          // 2k*c01*dz
            const float t2  = (f0.z * dz) * dz;   // k*c00*dz^2
            const float dyA = vyA - f1.w;
            const float dyB = dyA + 8.f * h;

            // Packed: lane0=row A, lane1=row B
            const u64 dy2 = pk2(dyA, dyB);
            const u64 bb2 = pfma(pkb(f0.w), dy2, pkb(bxz));
            const u64 cc2 = pfma(dy2, pfma(pkb(f0.y), dy2, pkb(t1)), pkb(t2));

            // Parabola max (log2): m_ub = cc + bb^2 * (0.25/|a|).
            const u64 ub2 = pfma(pmul(bb2, bb2), pkb(f2.z), cc2);
            float ubA, ubB;
            upk2(ub2, ubA, ubB);
            const bool dead = fmaxf(ubA, ubB) < -28.f;
            if (__all_sync(0xffffffffu, dead)) continue;

            const float r   = f2.w;
            const float r2s = r * r;
            const float r4s = r2s * r2s;

            const u64 a2  = pkb(f0.x);
            const u64 u02 = pkb(u0);
            const u64 m02 = pfma(pfma(a2, u02, bb2), u02, cc2);
            // step exponent g = h*(a*(2u0+h) + bb)
            const u64 g2  = pmul(pfma(a2, pkb(2.f * u0 + h), bb2), pkb(h));

            float m0A, m0B, gA, gB;
            upk2(m02, m0A, m0B);
            upk2(g2, gA, gB);
            gA = fminf(gA, 16.f);
            gB = fminf(gB, 16.f);

            u64 E0 = pk2(ex2_approx(m0A), ex2_approx(m0B));
            u64 G0 = pk2(ex2_approx(gA), ex2_approx(gB));
            const u64 rp  = pkb(r);
            const u64 rp2 = pkb(r2s);
            const u64 rp4 = pkb(r4s);
            const u64 w2  = pkb(f2.y);

            // Even/odd stride-2 chains: E_{v+2}=E_v*H_v ; H_{v+2}=H_v*r^4
            const u64 E1 = pmul(E0, G0);
            const u64 H0 = pmul(pmul(G0, G0), rp);
            const u64 H1 = pmul(H0, rp2);
            const u64 E2 = pmul(E0, H0);
            const u64 E3 = pmul(E1, H1);
            const u64 H2 = pmul(H0, rp4);
            const u64 H3 = pmul(H1, rp4);
            const u64 E4 = pmul(E2, H2);
            const u64 E5 = pmul(E3, H3);
            const u64 H4 = pmul(H2, rp4);
            const u64 H5 = pmul(H3, rp4);
            const u64 E6 = pmul(E4, H4);
            const u64 E7 = pmul(E5, H5);

            acc2[0] = pfma(E0, w2, acc2[0]);
            acc2[1] = pfma(E1, w2, acc2[1]);
            acc2[2] = pfma(E2, w2, acc2[2]);
            acc2[3] = pfma(E3, w2, acc2[3]);
            acc2[4] = pfma(E4, w2, acc2[4]);
            acc2[5] = pfma(E5, w2, acc2[5]);
            acc2[6] = pfma(E6, w2, acc2[6]);
            acc2[7] = pfma(E7, w2, acc2[7]);
        }
        __syncthreads();
    }

    float accA[RUNX], accB[RUNX];
#pragma unroll
    for (int v = 0; v < RUNX; v++) upk2(acc2[v], accA[v], accB[v]);

    const size_t vA = ((size_t)gz * DIMY + gy) * DIMX + gx;
    const size_t vB = ((size_t)gz * DIMY + (gy + 8)) * DIMX + gx;
    *reinterpret_cast<float4*>(out + vA)     = make_float4(accA[0], accA[1], accA[2], accA[3]);
    *reinterpret_cast<float4*>(out + vA + 4) = make_float4(accA[4], accA[5], accA[6], accA[7]);
    *reinterpret_cast<float4*>(out + vB)     = make_float4(accB[0], accB[1], accB[2], accB[3]);
    *reinterpret_cast<float4*>(out + vB + 4) = make_float4(accB[4], accB[5], accB[6], accB[7]);
}

extern "C" void kernel_launch(void* const* d_in, const int* in_sizes, int n_in,
                              void* d_out, int out_size) {
    const float* positions = (const float*)d_in[0];
    const float* scales    = (const float*)d_in[1];
    const float* rotations = (const float*)d_in[2];
    const float* density   = (const float*)d_in[3];
    const int N = in_sizes[3];

    precompute_kernel<<<(N + 255) / 256, 256>>>(positions, scales, rotations, density, N);

    dim3 grid(DIMX / RUNX, DIMY / TILE_Y, DIMZ / TILE_Z);  // (16, 8, 16) = 2048
    voxelize_kernel<<<grid, NTHREADS>>>((float*)d_out, N);
}